// round 4
// baseline (speedup 1.0000x reference)
#include <cuda_runtime.h>
#include <math.h>
#include <stdint.h>

#define BT_ 32
#define H_ 8
#define L_ 512
#define E_ 64
#define D_ 512
#define OUTN (BT_ * L_ * E_)

__device__ float g_Q[BT_ * H_ * L_ * E_];
__device__ float g_K[BT_ * H_ * L_ * E_];
__device__ float g_V[BT_ * H_ * L_ * E_];
__device__ float g_part[H_ * OUTN];

__device__ __forceinline__ uint32_t f2tf(float f) {
    uint32_t u;
    asm("cvt.rna.tf32.f32 %0, %1;" : "=r"(u) : "f"(f));
    return u;
}

__device__ __forceinline__ void mma8(float* c, const uint32_t* a, const uint32_t* b) {
    asm volatile(
        "mma.sync.aligned.m16n8k8.row.col.f32.tf32.tf32.f32 "
        "{%0,%1,%2,%3}, {%4,%5,%6,%7}, {%8,%9}, {%0,%1,%2,%3};\n"
        : "+f"(c[0]), "+f"(c[1]), "+f"(c[2]), "+f"(c[3])
        : "r"(a[0]), "r"(a[1]), "r"(a[2]), "r"(a[3]), "r"(b[0]), "r"(b[1]));
}

__device__ __forceinline__ void ldsm4(uint32_t* r, uint32_t saddr) {
    asm volatile("ldmatrix.sync.aligned.m8n8.x4.shared.b16 {%0,%1,%2,%3}, [%4];"
                 : "=r"(r[0]), "=r"(r[1]), "=r"(r[2]), "=r"(r[3]) : "r"(saddr));
}

// ---------------------------------------------------------------------------
// Fused projection GEMMs, tf32 + ldmatrix. grid.z selects (X, W, out).
// A smem [m][k] stride 20; B smem n-major [n][k] stride 20 (both tf32 bits).
// Register prefetch of next BK=16 tile. 256 thr / 8 warps, warp tile 32x64.
// ---------------------------------------------------------------------------
__global__ __launch_bounds__(256, 2) void proj3(const float* __restrict__ Xq,
                                                const float* __restrict__ Xk,
                                                const float* __restrict__ Xv,
                                                const float* __restrict__ Wq,
                                                const float* __restrict__ Wk,
                                                const float* __restrict__ Wv) {
    __shared__ uint32_t As[128 * 20];
    __shared__ uint32_t Bs[128 * 20];   // [n][k]

    const float* X;
    const float* W;
    float* out;
    if (blockIdx.z == 0)      { X = Xq; W = Wq; out = g_Q; }
    else if (blockIdx.z == 1) { X = Xk; W = Wk; out = g_K; }
    else                      { X = Xv; W = Wv; out = g_V; }

    const int tid = threadIdx.x;
    const int lane = tid & 31, wid = tid >> 5;
    const int g = lane >> 2, tig = lane & 3;
    const int warp_m = wid & 3, warp_n = wid >> 2;
    const int bm = blockIdx.x * 128;
    const int bn = blockIdx.y * 128;

    // ldmatrix per-thread address pieces
    const int r8 = lane & 7, j8 = lane >> 3;
    const int rowA_off = ((j8 & 1) << 3) + r8, colA_off = (j8 >> 1) << 2;
    const int rowB_off = ((j8 >> 1) << 3) + r8, colB_off = (j8 & 1) << 2;
    const uint32_t as_base = (uint32_t)__cvta_generic_to_shared(As);
    const uint32_t bs_base = (uint32_t)__cvta_generic_to_shared(Bs);

    // loader assignments
    const int arow = tid >> 1, ac4 = (tid & 1) * 8;        // A: 2 float4/thread (k 0..15)
    const int bnl = tid & 127, bkh = (tid >> 7) * 8;        // B: 8 scalar k-strided

    float a_pf[8], b_pf[8];

    {
        const float* ap = X + (size_t)(bm + arow) * 512;
        *(float4*)&a_pf[0] = *(const float4*)(ap + ac4);
        *(float4*)&a_pf[4] = *(const float4*)(ap + ac4 + 4);
        const float* bp = W + (size_t)bkh * 512 + bn + bnl;
#pragma unroll
        for (int i = 0; i < 8; i++) b_pf[i] = bp[(size_t)i * 512];
    }

    float c[2][8][4];
#pragma unroll
    for (int mt = 0; mt < 2; mt++)
#pragma unroll
        for (int nt = 0; nt < 8; nt++)
#pragma unroll
            for (int i = 0; i < 4; i++) c[mt][nt][i] = 0.f;

    for (int k0 = 0; k0 < 512; k0 += 16) {
        // store prefetched tile (converted)
        {
            uint4 u0 = make_uint4(f2tf(a_pf[0]), f2tf(a_pf[1]), f2tf(a_pf[2]), f2tf(a_pf[3]));
            uint4 u1 = make_uint4(f2tf(a_pf[4]), f2tf(a_pf[5]), f2tf(a_pf[6]), f2tf(a_pf[7]));
            *(uint4*)&As[arow * 20 + ac4] = u0;
            *(uint4*)&As[arow * 20 + ac4 + 4] = u1;
            uint4 w0 = make_uint4(f2tf(b_pf[0]), f2tf(b_pf[1]), f2tf(b_pf[2]), f2tf(b_pf[3]));
            uint4 w1 = make_uint4(f2tf(b_pf[4]), f2tf(b_pf[5]), f2tf(b_pf[6]), f2tf(b_pf[7]));
            *(uint4*)&Bs[bnl * 20 + bkh] = w0;
            *(uint4*)&Bs[bnl * 20 + bkh + 4] = w1;
        }
        __syncthreads();

        if (k0 + 16 < 512) {
            const float* ap = X + (size_t)(bm + arow) * 512 + k0 + 16;
            *(float4*)&a_pf[0] = *(const float4*)(ap + ac4);
            *(float4*)&a_pf[4] = *(const float4*)(ap + ac4 + 4);
            const float* bp = W + (size_t)(k0 + 16 + bkh) * 512 + bn + bnl;
#pragma unroll
            for (int i = 0; i < 8; i++) b_pf[i] = bp[(size_t)i * 512];
        }

#pragma unroll
        for (int kt = 0; kt < 2; kt++) {
            uint32_t a[2][4], br[16];
#pragma unroll
            for (int mt = 0; mt < 2; mt++)
                ldsm4(a[mt], as_base + 4u * ((warp_m * 32 + mt * 16 + rowA_off) * 20
                                             + kt * 8 + colA_off));
#pragma unroll
            for (int p = 0; p < 4; p++)
                ldsm4(&br[p * 4], bs_base + 4u * ((warp_n * 64 + p * 16 + rowB_off) * 20
                                                  + kt * 8 + colB_off));
#pragma unroll
            for (int mt = 0; mt < 2; mt++)
#pragma unroll
                for (int nt = 0; nt < 8; nt++)
                    mma8(c[mt][nt], a[mt], &br[(nt >> 1) * 4 + (nt & 1) * 2]);
        }
        __syncthreads();
    }

#pragma unroll
    for (int mt = 0; mt < 2; mt++) {
#pragma unroll
        for (int nt = 0; nt < 8; nt++) {
            int n = bn + warp_n * 64 + nt * 8 + 2 * tig;
            int h = n >> 6, e = n & 63;
            int r1 = bm + warp_m * 32 + mt * 16 + g;
            int bt1 = r1 >> 9, l1 = r1 & 511;
            *(float2*)&out[((size_t)(bt1 * 8 + h) * 512 + l1) * 64 + e] =
                make_float2(c[mt][nt][0], c[mt][nt][1]);
            int r2 = r1 + 8;
            int bt2 = r2 >> 9, l2 = r2 & 511;
            *(float2*)&out[((size_t)(bt2 * 8 + h) * 512 + l2) * 64 + e] =
                make_float2(c[mt][nt][2], c[mt][nt][3]);
        }
    }
}

// ---------------------------------------------------------------------------
// Flash attention per head with ldmatrix fragments.
// Qs/Ks [row][e] stride 68 (Qs reused as Ps), Vs e-major [e][s] stride 84.
// Grid (L/64, BT, H), 128 thr / 4 warps. Partials to g_part[h].
// ---------------------------------------------------------------------------
__global__ __launch_bounds__(128, 3) void attn3(const float* __restrict__ mask,
                                                const float* __restrict__ w_head,
                                                const float* __restrict__ tau_p,
                                                const float* __restrict__ delta_p) {
    extern __shared__ uint32_t smu[];
    uint32_t* Qs = smu;                  // 64*68 (reused as Ps)
    uint32_t* Ks = smu + 64 * 68;        // 64*68
    uint32_t* Vs = smu + 2 * 64 * 68;    // 64*84

    const int tid = threadIdx.x;
    const int lane = tid & 31, wid = tid >> 5;
    const int g = lane >> 2, tig = lane & 3;
    const int bt = blockIdx.y;
    const int h  = blockIdx.z;
    const int row0 = blockIdx.x * 64;
    const int wrow = wid * 16;

    const int r8 = lane & 7, j8 = lane >> 3;
    const int rowA_off = ((j8 & 1) << 3) + r8, colA_off = (j8 >> 1) << 2;
    const int rowB_off = ((j8 >> 1) << 3) + r8, colB_off = (j8 & 1) << 2;
    const uint32_t qs_base = (uint32_t)__cvta_generic_to_shared(Qs);
    const uint32_t ks_base = (uint32_t)__cvta_generic_to_shared(Ks);
    const uint32_t vs_base = (uint32_t)__cvta_generic_to_shared(Vs);

    const float a_scl = tau_p[0] * 0.125f;
    const float c_add = delta_p[0] * 0.125f;

    const float* Qg = g_Q + (((size_t)(bt * 8 + h) * 512) + row0) * 64;
    const float* Kg = g_K + ((size_t)(bt * 8 + h) * 512) * 64;
    const float* Vg = g_V + ((size_t)(bt * 8 + h) * 512) * 64;

    // Q tile
#pragma unroll
    for (int it = 0; it < 8; it++) {
        int f = it * 128 + tid;
        int row = f >> 4, cc = (f & 15) * 4;
        float4 v = *(const float4*)(Qg + row * 64 + cc);
        *(uint4*)&Qs[row * 68 + cc] =
            make_uint4(f2tf(v.x), f2tf(v.y), f2tf(v.z), f2tf(v.w));
    }
    __syncthreads();

    // Preload Q fragments (8 LDSM.x4), then Qs becomes Ps
    uint32_t qa[8][4];
#pragma unroll
    for (int kt = 0; kt < 8; kt++)
        ldsm4(qa[kt], qs_base + 4u * ((wrow + rowA_off) * 68 + kt * 8 + colA_off));

    float m1 = -INFINITY, m2 = -INFINITY, l1 = 0.f, l2 = 0.f;
    float oacc[8][4];
#pragma unroll
    for (int nt = 0; nt < 8; nt++)
#pragma unroll
        for (int i = 0; i < 4; i++) oacc[nt][i] = 0.f;

    // V loader assignment: e-major transpose
    const int e_l = tid & 63, s_h = (tid >> 6) * 32;

    for (int jb = 0; jb < 8; jb++) {
        __syncthreads();
        // K tile (k-major) + V tile (e-major transposed)
#pragma unroll
        for (int it = 0; it < 8; it++) {
            int f = it * 128 + tid;
            int row = f >> 4, cc = (f & 15) * 4;
            float4 vk = *(const float4*)(Kg + (jb * 64 + row) * 64 + cc);
            *(uint4*)&Ks[row * 68 + cc] =
                make_uint4(f2tf(vk.x), f2tf(vk.y), f2tf(vk.z), f2tf(vk.w));
        }
#pragma unroll
        for (int cb = 0; cb < 8; cb++) {
            uint4 u;
            u.x = f2tf(Vg[(size_t)(jb * 64 + s_h + cb * 4 + 0) * 64 + e_l]);
            u.y = f2tf(Vg[(size_t)(jb * 64 + s_h + cb * 4 + 1) * 64 + e_l]);
            u.z = f2tf(Vg[(size_t)(jb * 64 + s_h + cb * 4 + 2) * 64 + e_l]);
            u.w = f2tf(Vg[(size_t)(jb * 64 + s_h + cb * 4 + 3) * 64 + e_l]);
            *(uint4*)&Vs[e_l * 84 + s_h + cb * 4] = u;
        }
        __syncthreads();

        // S = Q K^T
        float sacc[8][4];
#pragma unroll
        for (int nt = 0; nt < 8; nt++)
#pragma unroll
            for (int i = 0; i < 4; i++) sacc[nt][i] = 0.f;
#pragma unroll
        for (int kt = 0; kt < 8; kt++) {
            uint32_t kb[16];
#pragma unroll
            for (int p = 0; p < 4; p++)
                ldsm4(&kb[p * 4], ks_base + 4u * ((p * 16 + rowB_off) * 68
                                                  + kt * 8 + colB_off));
#pragma unroll
            for (int nt = 0; nt < 8; nt++)
                mma8(sacc[nt], qa[kt], &kb[(nt >> 1) * 4 + (nt & 1) * 2]);
        }

        const int gr1 = row0 + wrow + g;
        const int gr2 = gr1 + 8;
#pragma unroll
        for (int nt = 0; nt < 8; nt++) {
            int gc = jb * 64 + nt * 8 + 2 * tig;
            float2 mk1 = *(const float2*)(mask + (size_t)gr1 * 512 + gc);
            float2 mk2 = *(const float2*)(mask + (size_t)gr2 * 512 + gc);
            sacc[nt][0] = fmaf(a_scl, sacc[nt][0], c_add) * mk1.x;
            sacc[nt][1] = fmaf(a_scl, sacc[nt][1], c_add) * mk1.y;
            sacc[nt][2] = fmaf(a_scl, sacc[nt][2], c_add) * mk2.x;
            sacc[nt][3] = fmaf(a_scl, sacc[nt][3], c_add) * mk2.y;
        }

        // online softmax
        float rm1 = -INFINITY, rm2 = -INFINITY;
#pragma unroll
        for (int nt = 0; nt < 8; nt++) {
            rm1 = fmaxf(rm1, fmaxf(sacc[nt][0], sacc[nt][1]));
            rm2 = fmaxf(rm2, fmaxf(sacc[nt][2], sacc[nt][3]));
        }
#pragma unroll
        for (int off = 1; off < 4; off <<= 1) {
            rm1 = fmaxf(rm1, __shfl_xor_sync(0xffffffffu, rm1, off));
            rm2 = fmaxf(rm2, __shfl_xor_sync(0xffffffffu, rm2, off));
        }
        float nm1 = fmaxf(m1, rm1), nm2 = fmaxf(m2, rm2);
        float fac1 = __expf(m1 - nm1), fac2 = __expf(m2 - nm2);
        float rs1 = 0.f, rs2 = 0.f;
#pragma unroll
        for (int nt = 0; nt < 8; nt++) {
            sacc[nt][0] = __expf(sacc[nt][0] - nm1);
            sacc[nt][1] = __expf(sacc[nt][1] - nm1);
            sacc[nt][2] = __expf(sacc[nt][2] - nm2);
            sacc[nt][3] = __expf(sacc[nt][3] - nm2);
            rs1 += sacc[nt][0] + sacc[nt][1];
            rs2 += sacc[nt][2] + sacc[nt][3];
        }
#pragma unroll
        for (int off = 1; off < 4; off <<= 1) {
            rs1 += __shfl_xor_sync(0xffffffffu, rs1, off);
            rs2 += __shfl_xor_sync(0xffffffffu, rs2, off);
        }
        l1 = l1 * fac1 + rs1;  m1 = nm1;
        l2 = l2 * fac2 + rs2;  m2 = nm2;
#pragma unroll
        for (int nt = 0; nt < 8; nt++) {
            oacc[nt][0] *= fac1;  oacc[nt][1] *= fac1;
            oacc[nt][2] *= fac2;  oacc[nt][3] *= fac2;
        }

        // stage P (tf32) into Ps=Qs (warp-private rows)
#pragma unroll
        for (int nt = 0; nt < 8; nt++) {
            int cc = nt * 8 + 2 * tig;
            *(uint2*)&Qs[(wrow + g) * 68 + cc] =
                make_uint2(f2tf(sacc[nt][0]), f2tf(sacc[nt][1]));
            *(uint2*)&Qs[(wrow + g + 8) * 68 + cc] =
                make_uint2(f2tf(sacc[nt][2]), f2tf(sacc[nt][3]));
        }
        __syncwarp();

        // O += P V
#pragma unroll
        for (int kt = 0; kt < 8; kt++) {
            uint32_t pa[4], vb[16];
            ldsm4(pa, qs_base + 4u * ((wrow + rowA_off) * 68 + kt * 8 + colA_off));
#pragma unroll
            for (int p = 0; p < 4; p++)
                ldsm4(&vb[p * 4], vs_base + 4u * ((p * 16 + rowB_off) * 84
                                                  + kt * 8 + colB_off));
#pragma unroll
            for (int nt = 0; nt < 8; nt++)
                mma8(oacc[nt], pa, &vb[(nt >> 1) * 4 + (nt & 1) * 2]);
        }
    }

    const float wh = w_head[h];
    const float i1 = wh / l1, i2 = wh / l2;
    float* po = g_part + (size_t)h * OUTN;
    const int l1r = row0 + wrow + g, l2r = l1r + 8;
#pragma unroll
    for (int nt = 0; nt < 8; nt++) {
        int e = nt * 8 + 2 * tig;
        *(float2*)&po[((size_t)bt * 512 + l1r) * 64 + e] =
            make_float2(oacc[nt][0] * i1, oacc[nt][1] * i1);
        *(float2*)&po[((size_t)bt * 512 + l2r) * 64 + e] =
            make_float2(oacc[nt][2] * i2, oacc[nt][3] * i2);
    }
}

__global__ __launch_bounds__(256) void reduce_out(float* __restrict__ out) {
    int i = blockIdx.x * 256 + threadIdx.x;
    const float4* p = (const float4*)g_part;
    float4 s = p[i];
#pragma unroll
    for (int h = 1; h < 8; h++) {
        float4 t = p[(size_t)h * (OUTN / 4) + i];
        s.x += t.x; s.y += t.y; s.z += t.z; s.w += t.w;
    }
    ((float4*)out)[i] = s;
}

extern "C" void kernel_launch(void* const* d_in, const int* in_sizes, int n_in,
                              void* d_out, int out_size) {
    const float* queries = (const float*)d_in[0];
    const float* keys    = (const float*)d_in[1];
    const float* values  = (const float*)d_in[2];
    const float* mask    = (const float*)d_in[3];
    const float* Wq      = (const float*)d_in[4];
    const float* Wk      = (const float*)d_in[5];
    const float* Wv      = (const float*)d_in[6];
    const float* w_head  = (const float*)d_in[7];
    const float* tau     = (const float*)d_in[8];
    const float* delta   = (const float*)d_in[9];
    float* out = (float*)d_out;

    dim3 pgrid(128, 4, 3);
    proj3<<<pgrid, 256>>>(queries, keys, values, Wq, Wk, Wv);

    const int smem = (2 * 64 * 68 + 64 * 84) * (int)sizeof(uint32_t);  // 56320 B
    cudaFuncSetAttribute(attn3, cudaFuncAttributeMaxDynamicSharedMemorySize, smem);
    dim3 agrid(8, 32, 8);
    attn3<<<agrid, 128, smem>>>(mask, w_head, tau, delta);

    reduce_out<<<OUTN / 4 / 256, 256>>>(out);
}

// round 7
// speedup vs baseline: 1.2405x; 1.2405x over previous
#include <cuda_runtime.h>
#include <math.h>
#include <stdint.h>

#define BT_ 32
#define H_ 8
#define L_ 512
#define E_ 64
#define D_ 512
#define OUTN (BT_ * L_ * E_)

__device__ float g_Q[BT_ * H_ * L_ * E_];
__device__ float g_K[BT_ * H_ * L_ * E_];
__device__ float g_V[BT_ * H_ * L_ * E_];
__device__ float g_part[H_ * OUTN];

__device__ __forceinline__ uint32_t f2tf(float f) {
    uint32_t u;
    asm("cvt.rna.tf32.f32 %0, %1;" : "=r"(u) : "f"(f));
    return u;
}

__device__ __forceinline__ void mma8(float* c, const uint32_t* a, const uint32_t* b) {
    asm volatile(
        "mma.sync.aligned.m16n8k8.row.col.f32.tf32.tf32.f32 "
        "{%0,%1,%2,%3}, {%4,%5,%6,%7}, {%8,%9}, {%0,%1,%2,%3};\n"
        : "+f"(c[0]), "+f"(c[1]), "+f"(c[2]), "+f"(c[3])
        : "r"(a[0]), "r"(a[1]), "r"(a[2]), "r"(a[3]), "r"(b[0]), "r"(b[1]));
}

// ---------------------------------------------------------------------------
// Fused projection GEMMs, tf32, double-buffered smem, LDS.64 A-fragments via
// consistent-k relabeling (lane tig handles k = 2tig, 2tig+1).
// As stride 40 ([m][k]), Bs stride 132 ([k][n]). 256 thr / 8 warps, 32x64/warp.
// ---------------------------------------------------------------------------
#define AS_ST 40
#define BS_ST 132
#define AS_SZ (128 * AS_ST)
#define BS_SZ (16 * BS_ST)

__global__ __launch_bounds__(256, 2) void proj3(const float* __restrict__ Xq,
                                                const float* __restrict__ Xk,
                                                const float* __restrict__ Xv,
                                                const float* __restrict__ Wq,
                                                const float* __restrict__ Wk,
                                                const float* __restrict__ Wv) {
    extern __shared__ uint32_t psm[];
    uint32_t* As = psm;                       // [2][AS_SZ]
    uint32_t* Bs = psm + 2 * AS_SZ;           // [2][BS_SZ]

    const float* X;
    const float* W;
    float* out;
    if (blockIdx.z == 0)      { X = Xq; W = Wq; out = g_Q; }
    else if (blockIdx.z == 1) { X = Xk; W = Wk; out = g_K; }
    else                      { X = Xv; W = Wv; out = g_V; }

    const int tid = threadIdx.x;
    const int lane = tid & 31, wid = tid >> 5;
    const int g = lane >> 2, tig = lane & 3;
    const int warp_m = wid & 3, warp_n = wid >> 2;
    const int bm = blockIdx.x * 128;
    const int bn = blockIdx.y * 128;

    // loader assignments
    const int ar = tid >> 2, ac = (tid & 3) * 4;      // A rows ar, ar+64
    const int bwr = tid >> 5, bc4 = (tid & 31) * 4;   // B rows bwr, bwr+8

    float a_pf[8], b_pf[8];
    {
        const float* ap = X + (size_t)(bm + ar) * 512 + ac;
        *(float4*)&a_pf[0] = *(const float4*)ap;
        *(float4*)&a_pf[4] = *(const float4*)(ap + (size_t)64 * 512);
        const float* bp = W + (size_t)bwr * 512 + bn + bc4;
        *(float4*)&b_pf[0] = *(const float4*)bp;
        *(float4*)&b_pf[4] = *(const float4*)(bp + (size_t)8 * 512);
    }
    // store tile 0 into buffer 0
    {
        *(uint4*)&As[ar * AS_ST + ac] =
            make_uint4(f2tf(a_pf[0]), f2tf(a_pf[1]), f2tf(a_pf[2]), f2tf(a_pf[3]));
        *(uint4*)&As[(ar + 64) * AS_ST + ac] =
            make_uint4(f2tf(a_pf[4]), f2tf(a_pf[5]), f2tf(a_pf[6]), f2tf(a_pf[7]));
        *(uint4*)&Bs[bwr * BS_ST + bc4] =
            make_uint4(f2tf(b_pf[0]), f2tf(b_pf[1]), f2tf(b_pf[2]), f2tf(b_pf[3]));
        *(uint4*)&Bs[(bwr + 8) * BS_ST + bc4] =
            make_uint4(f2tf(b_pf[4]), f2tf(b_pf[5]), f2tf(b_pf[6]), f2tf(b_pf[7]));
    }

    float c[2][8][4];
#pragma unroll
    for (int mt = 0; mt < 2; mt++)
#pragma unroll
        for (int nt = 0; nt < 8; nt++)
#pragma unroll
            for (int i = 0; i < 4; i++) c[mt][nt][i] = 0.f;

    for (int it = 0; it < 32; it++) {
        __syncthreads();   // buffer (it&1) fully stored
        const uint32_t* Ac = As + (it & 1) * AS_SZ;
        const uint32_t* Bc = Bs + (it & 1) * BS_SZ;

        if (it + 1 < 32) {
            int k0 = (it + 1) * 16;
            const float* ap = X + (size_t)(bm + ar) * 512 + k0 + ac;
            *(float4*)&a_pf[0] = *(const float4*)ap;
            *(float4*)&a_pf[4] = *(const float4*)(ap + (size_t)64 * 512);
            const float* bp = W + (size_t)(k0 + bwr) * 512 + bn + bc4;
            *(float4*)&b_pf[0] = *(const float4*)bp;
            *(float4*)&b_pf[4] = *(const float4*)(bp + (size_t)8 * 512);
        }

#pragma unroll
        for (int kt = 0; kt < 2; kt++) {
            uint32_t a[2][4];
#pragma unroll
            for (int mt = 0; mt < 2; mt++) {
                int r = warp_m * 32 + mt * 16 + g;
                uint2 u0 = *(const uint2*)&Ac[r * AS_ST + kt * 8 + 2 * tig];
                uint2 u1 = *(const uint2*)&Ac[(r + 8) * AS_ST + kt * 8 + 2 * tig];
                a[mt][0] = u0.x; a[mt][1] = u1.x; a[mt][2] = u0.y; a[mt][3] = u1.y;
            }
#pragma unroll
            for (int nt = 0; nt < 8; nt++) {
                int col = warp_n * 64 + nt * 8 + g;
                uint32_t b[2];
                b[0] = Bc[(kt * 8 + 2 * tig) * BS_ST + col];
                b[1] = Bc[(kt * 8 + 2 * tig + 1) * BS_ST + col];
#pragma unroll
                for (int mt = 0; mt < 2; mt++) mma8(c[mt][nt], a[mt], b);
            }
        }

        if (it + 1 < 32) {
            uint32_t* An = As + ((it + 1) & 1) * AS_SZ;
            uint32_t* Bn = Bs + ((it + 1) & 1) * BS_SZ;
            *(uint4*)&An[ar * AS_ST + ac] =
                make_uint4(f2tf(a_pf[0]), f2tf(a_pf[1]), f2tf(a_pf[2]), f2tf(a_pf[3]));
            *(uint4*)&An[(ar + 64) * AS_ST + ac] =
                make_uint4(f2tf(a_pf[4]), f2tf(a_pf[5]), f2tf(a_pf[6]), f2tf(a_pf[7]));
            *(uint4*)&Bn[bwr * BS_ST + bc4] =
                make_uint4(f2tf(b_pf[0]), f2tf(b_pf[1]), f2tf(b_pf[2]), f2tf(b_pf[3]));
            *(uint4*)&Bn[(bwr + 8) * BS_ST + bc4] =
                make_uint4(f2tf(b_pf[4]), f2tf(b_pf[5]), f2tf(b_pf[6]), f2tf(b_pf[7]));
        }
    }

#pragma unroll
    for (int mt = 0; mt < 2; mt++) {
#pragma unroll
        for (int nt = 0; nt < 8; nt++) {
            int n = bn + warp_n * 64 + nt * 8 + 2 * tig;
            int h = n >> 6, e = n & 63;
            int r1 = bm + warp_m * 32 + mt * 16 + g;
            int bt1 = r1 >> 9, l1 = r1 & 511;
            *(float2*)&out[((size_t)(bt1 * 8 + h) * 512 + l1) * 64 + e] =
                make_float2(c[mt][nt][0], c[mt][nt][1]);
            int r2 = r1 + 8;
            int bt2 = r2 >> 9, l2 = r2 & 511;
            *(float2*)&out[((size_t)(bt2 * 8 + h) * 512 + l2) * 64 + e] =
                make_float2(c[mt][nt][2], c[mt][nt][3]);
        }
    }
}

// ---------------------------------------------------------------------------
// Flash attention per head, consistent-k LDS.64 fragments.
// Qs/Ks stride 72 (Qs reused as Ps), Vs stride 68. Grid (L/64, BT, H).
// ---------------------------------------------------------------------------
#define QS_ST 72
#define VS_ST 68

__global__ __launch_bounds__(128, 3) void attn3(const float* __restrict__ mask,
                                                const float* __restrict__ w_head,
                                                const float* __restrict__ tau_p,
                                                const float* __restrict__ delta_p) {
    extern __shared__ uint32_t smu[];
    uint32_t* Qs = smu;                        // 64*72 (reused as Ps)
    uint32_t* Ks = smu + 64 * QS_ST;           // 64*72
    uint32_t* Vs = smu + 2 * 64 * QS_ST;       // 64*68

    const int tid = threadIdx.x;
    const int lane = tid & 31, wid = tid >> 5;
    const int g = lane >> 2, tig = lane & 3;
    const int bt = blockIdx.y;
    const int h  = blockIdx.z;
    const int row0 = blockIdx.x * 64;
    const int wrow = wid * 16;

    const float a_scl = tau_p[0] * 0.125f;
    const float c_add = delta_p[0] * 0.125f;

    const float* Qg = g_Q + (((size_t)(bt * 8 + h) * 512) + row0) * 64;
    const float* Kg = g_K + ((size_t)(bt * 8 + h) * 512) * 64;
    const float* Vg = g_V + ((size_t)(bt * 8 + h) * 512) * 64;

    // Q tile
#pragma unroll
    for (int it = 0; it < 8; it++) {
        int f = it * 128 + tid;
        int row = f >> 4, cc = (f & 15) * 4;
        float4 v = *(const float4*)(Qg + row * 64 + cc);
        *(uint4*)&Qs[row * QS_ST + cc] =
            make_uint4(f2tf(v.x), f2tf(v.y), f2tf(v.z), f2tf(v.w));
    }
    __syncthreads();

    // Preload Q fragments (LDS.64 pairs), then Qs becomes Ps
    uint32_t qa[8][4];
#pragma unroll
    for (int kt = 0; kt < 8; kt++) {
        uint2 u0 = *(const uint2*)&Qs[(wrow + g) * QS_ST + kt * 8 + 2 * tig];
        uint2 u1 = *(const uint2*)&Qs[(wrow + g + 8) * QS_ST + kt * 8 + 2 * tig];
        qa[kt][0] = u0.x; qa[kt][1] = u1.x; qa[kt][2] = u0.y; qa[kt][3] = u1.y;
    }

    float m1 = -INFINITY, m2 = -INFINITY, l1 = 0.f, l2 = 0.f;
    float oacc[8][4];
#pragma unroll
    for (int nt = 0; nt < 8; nt++)
#pragma unroll
        for (int i = 0; i < 4; i++) oacc[nt][i] = 0.f;

    for (int jb = 0; jb < 8; jb++) {
        __syncthreads();
#pragma unroll
        for (int it = 0; it < 8; it++) {
            int f = it * 128 + tid;
            int row = f >> 4, cc = (f & 15) * 4;
            float4 vk = *(const float4*)(Kg + (jb * 64 + row) * 64 + cc);
            *(uint4*)&Ks[row * QS_ST + cc] =
                make_uint4(f2tf(vk.x), f2tf(vk.y), f2tf(vk.z), f2tf(vk.w));
            float4 vv = *(const float4*)(Vg + (jb * 64 + row) * 64 + cc);
            *(uint4*)&Vs[row * VS_ST + cc] =
                make_uint4(f2tf(vv.x), f2tf(vv.y), f2tf(vv.z), f2tf(vv.w));
        }
        __syncthreads();

        // S = Q K^T
        float sacc[8][4];
#pragma unroll
        for (int nt = 0; nt < 8; nt++)
#pragma unroll
            for (int i = 0; i < 4; i++) sacc[nt][i] = 0.f;
#pragma unroll
        for (int kt = 0; kt < 8; kt++) {
#pragma unroll
            for (int nt = 0; nt < 8; nt++) {
                uint2 kb = *(const uint2*)&Ks[(nt * 8 + g) * QS_ST + kt * 8 + 2 * tig];
                mma8(sacc[nt], qa[kt], (const uint32_t*)&kb);
            }
        }

        const int gr1 = row0 + wrow + g;
        const int gr2 = gr1 + 8;
#pragma unroll
        for (int nt = 0; nt < 8; nt++) {
            int gc = jb * 64 + nt * 8 + 2 * tig;
            float2 mk1 = *(const float2*)(mask + (size_t)gr1 * 512 + gc);
            float2 mk2 = *(const float2*)(mask + (size_t)gr2 * 512 + gc);
            sacc[nt][0] = fmaf(a_scl, sacc[nt][0], c_add) * mk1.x;
            sacc[nt][1] = fmaf(a_scl, sacc[nt][1], c_add) * mk1.y;
            sacc[nt][2] = fmaf(a_scl, sacc[nt][2], c_add) * mk2.x;
            sacc[nt][3] = fmaf(a_scl, sacc[nt][3], c_add) * mk2.y;
        }

        // online softmax
        float rm1 = -INFINITY, rm2 = -INFINITY;
#pragma unroll
        for (int nt = 0; nt < 8; nt++) {
            rm1 = fmaxf(rm1, fmaxf(sacc[nt][0], sacc[nt][1]));
            rm2 = fmaxf(rm2, fmaxf(sacc[nt][2], sacc[nt][3]));
        }
#pragma unroll
        for (int off = 1; off < 4; off <<= 1) {
            rm1 = fmaxf(rm1, __shfl_xor_sync(0xffffffffu, rm1, off));
            rm2 = fmaxf(rm2, __shfl_xor_sync(0xffffffffu, rm2, off));
        }
        float nm1 = fmaxf(m1, rm1), nm2 = fmaxf(m2, rm2);
        float fac1 = __expf(m1 - nm1), fac2 = __expf(m2 - nm2);
        float rs1 = 0.f, rs2 = 0.f;
#pragma unroll
        for (int nt = 0; nt < 8; nt++) {
            sacc[nt][0] = __expf(sacc[nt][0] - nm1);
            sacc[nt][1] = __expf(sacc[nt][1] - nm1);
            sacc[nt][2] = __expf(sacc[nt][2] - nm2);
            sacc[nt][3] = __expf(sacc[nt][3] - nm2);
            rs1 += sacc[nt][0] + sacc[nt][1];
            rs2 += sacc[nt][2] + sacc[nt][3];
        }
#pragma unroll
        for (int off = 1; off < 4; off <<= 1) {
            rs1 += __shfl_xor_sync(0xffffffffu, rs1, off);
            rs2 += __shfl_xor_sync(0xffffffffu, rs2, off);
        }
        l1 = l1 * fac1 + rs1;  m1 = nm1;
        l2 = l2 * fac2 + rs2;  m2 = nm2;
#pragma unroll
        for (int nt = 0; nt < 8; nt++) {
            oacc[nt][0] *= fac1;  oacc[nt][1] *= fac1;
            oacc[nt][2] *= fac2;  oacc[nt][3] *= fac2;
        }

        // stage P (tf32) into Ps=Qs; C-frag cols 2tig,2tig+1 are adjacent
#pragma unroll
        for (int nt = 0; nt < 8; nt++) {
            int cc = nt * 8 + 2 * tig;
            *(uint2*)&Qs[(wrow + g) * QS_ST + cc] =
                make_uint2(f2tf(sacc[nt][0]), f2tf(sacc[nt][1]));
            *(uint2*)&Qs[(wrow + g + 8) * QS_ST + cc] =
                make_uint2(f2tf(sacc[nt][2]), f2tf(sacc[nt][3]));
        }
        __syncwarp();

        // O += P V   (pa LDS.64 pairs; vb scalar, rows 2tig / 2tig+1)
#pragma unroll
        for (int kt = 0; kt < 8; kt++) {
            uint32_t pa[4];
            {
                uint2 u0 = *(const uint2*)&Qs[(wrow + g) * QS_ST + kt * 8 + 2 * tig];
                uint2 u1 = *(const uint2*)&Qs[(wrow + g + 8) * QS_ST + kt * 8 + 2 * tig];
                pa[0] = u0.x; pa[1] = u1.x; pa[2] = u0.y; pa[3] = u1.y;
            }
#pragma unroll
            for (int nt = 0; nt < 8; nt++) {
                uint32_t vb[2];
                vb[0] = Vs[(kt * 8 + 2 * tig) * VS_ST + nt * 8 + g];
                vb[1] = Vs[(kt * 8 + 2 * tig + 1) * VS_ST + nt * 8 + g];
                mma8(oacc[nt], pa, vb);
            }
        }
    }

    const float wh = w_head[h];
    const float i1 = wh / l1, i2 = wh / l2;
    float* po = g_part + (size_t)h * OUTN;
    const int l1r = row0 + wrow + g, l2r = l1r + 8;
#pragma unroll
    for (int nt = 0; nt < 8; nt++) {
        int e = nt * 8 + 2 * tig;
        *(float2*)&po[((size_t)bt * 512 + l1r) * 64 + e] =
            make_float2(oacc[nt][0] * i1, oacc[nt][1] * i1);
        *(float2*)&po[((size_t)bt * 512 + l2r) * 64 + e] =
            make_float2(oacc[nt][2] * i2, oacc[nt][3] * i2);
    }
}

__global__ __launch_bounds__(256) void reduce_out(float* __restrict__ out) {
    int i = blockIdx.x * 256 + threadIdx.x;
    const float4* p = (const float4*)g_part;
    float4 s = p[i];
#pragma unroll
    for (int h = 1; h < 8; h++) {
        float4 t = p[(size_t)h * (OUTN / 4) + i];
        s.x += t.x; s.y += t.y; s.z += t.z; s.w += t.w;
    }
    ((float4*)out)[i] = s;
}

extern "C" void kernel_launch(void* const* d_in, const int* in_sizes, int n_in,
                              void* d_out, int out_size) {
    const float* queries = (const float*)d_in[0];
    const float* keys    = (const float*)d_in[1];
    const float* values  = (const float*)d_in[2];
    const float* mask    = (const float*)d_in[3];
    const float* Wq      = (const float*)d_in[4];
    const float* Wk      = (const float*)d_in[5];
    const float* Wv      = (const float*)d_in[6];
    const float* w_head  = (const float*)d_in[7];
    const float* tau     = (const float*)d_in[8];
    const float* delta   = (const float*)d_in[9];
    float* out = (float*)d_out;

    const int psmem = (2 * AS_SZ + 2 * BS_SZ) * (int)sizeof(uint32_t);  // 57856 B
    cudaFuncSetAttribute(proj3, cudaFuncAttributeMaxDynamicSharedMemorySize, psmem);
    dim3 pgrid(128, 4, 3);
    proj3<<<pgrid, 256, psmem>>>(queries, keys, values, Wq, Wk, Wv);

    const int asmem = (2 * 64 * QS_ST + 64 * VS_ST) * (int)sizeof(uint32_t);  // 54272 B
    cudaFuncSetAttribute(attn3, cudaFuncAttributeMaxDynamicSharedMemorySize, asmem);
    dim3 agrid(8, 32, 8);
    attn3<<<agrid, 128, asmem>>>(mask, w_head, tau, delta);

    reduce_out<<<OUTN / 4 / 256, 256>>>(out);
}

// round 9
// speedup vs baseline: 1.4357x; 1.1573x over previous
#include <cuda_runtime.h>
#include <math.h>
#include <stdint.h>

#define BT_ 32
#define H_ 8
#define L_ 512
#define E_ 64
#define D_ 512
#define OUTN (BT_ * L_ * E_)

// Q/K/V stored as tf32 bit patterns (pre-converted)
__device__ uint32_t g_Q[BT_ * H_ * L_ * E_];
__device__ uint32_t g_K[BT_ * H_ * L_ * E_];
__device__ uint32_t g_V[BT_ * H_ * L_ * E_];
__device__ uint32_t g_Wt[3 * D_ * D_];          // W transposed, n-major, tf32 bits
__device__ float g_part[H_ * OUTN];

__device__ __forceinline__ uint32_t f2tf(float f) {
    uint32_t u;
    asm("cvt.rna.tf32.f32 %0, %1;" : "=r"(u) : "f"(f));
    return u;
}

__device__ __forceinline__ void mma8(float* c, const uint32_t* a, const uint32_t* b) {
    asm volatile(
        "mma.sync.aligned.m16n8k8.row.col.f32.tf32.tf32.f32 "
        "{%0,%1,%2,%3}, {%4,%5,%6,%7}, {%8,%9}, {%0,%1,%2,%3};\n"
        : "+f"(c[0]), "+f"(c[1]), "+f"(c[2]), "+f"(c[3])
        : "r"(a[0]), "r"(a[1]), "r"(a[2]), "r"(a[3]), "r"(b[0]), "r"(b[1]));
}

// ---------------------------------------------------------------------------
// W transpose + tf32 convert: g_Wt[z][n][k] = tf32(W_z[k][n]). Grid (8,8,3).
// ---------------------------------------------------------------------------
__global__ __launch_bounds__(256) void wtrans(const float* __restrict__ Wq,
                                              const float* __restrict__ Wk,
                                              const float* __restrict__ Wv) {
    __shared__ float t[64][65];
    const float* W = (blockIdx.z == 0) ? Wq : (blockIdx.z == 1) ? Wk : Wv;
    uint32_t* outp = g_Wt + (size_t)blockIdx.z * D_ * D_;
    const int k0 = blockIdx.x * 64, n0 = blockIdx.y * 64;
    const int tid = threadIdx.x;
#pragma unroll
    for (int i = 0; i < 16; i++) {
        int idx = i * 256 + tid;
        int r = idx >> 6, c = idx & 63;
        t[r][c] = W[(size_t)(k0 + r) * 512 + n0 + c];
    }
    __syncthreads();
#pragma unroll
    for (int i = 0; i < 16; i++) {
        int idx = i * 256 + tid;
        int r = idx >> 6, c = idx & 63;
        outp[(size_t)(n0 + r) * 512 + k0 + c] = f2tf(t[c][r]);
    }
}

// ---------------------------------------------------------------------------
// Fused projection GEMMs, tf32, double-buffered. A smem [m][k] stride 40,
// B smem [n][k] stride 40 (from pre-transposed g_Wt). All fragment loads are
// conflict-free LDS.64 via consistent-k relabeling (lane tig -> k=2tig,2tig+1).
// 256 thr / 8 warps, warp tile 32x64. Epilogue stores tf32 bits.
// ---------------------------------------------------------------------------
#define PS_ST 40
#define PT_SZ (128 * PS_ST)

__global__ __launch_bounds__(256, 2) void proj3(const float* __restrict__ Xq,
                                                const float* __restrict__ Xk,
                                                const float* __restrict__ Xv) {
    extern __shared__ uint32_t psm[];
    uint32_t* As = psm;                 // [2][PT_SZ]
    uint32_t* Bs = psm + 2 * PT_SZ;     // [2][PT_SZ]

    const float* X;
    const uint32_t* Wt;
    uint32_t* outp;
    if (blockIdx.z == 0)      { X = Xq; Wt = g_Wt;                outp = g_Q; }
    else if (blockIdx.z == 1) { X = Xk; Wt = g_Wt + D_ * D_;      outp = g_K; }
    else                      { X = Xv; Wt = g_Wt + 2 * D_ * D_;  outp = g_V; }

    const int tid = threadIdx.x;
    const int lane = tid & 31, wid = tid >> 5;
    const int g = lane >> 2, tig = lane & 3;
    const int warp_m = wid & 3, warp_n = wid >> 2;
    const int bm = blockIdx.x * 128;
    const int bn = blockIdx.y * 128;

    // loader: rows r, r+64; 4 words along k at ac
    const int lr = tid >> 2, lc = (tid & 3) * 4;

    float a_pf[8];
    uint4 b_pf[2];
    {
        const float* ap = X + (size_t)(bm + lr) * 512 + lc;
        *(float4*)&a_pf[0] = *(const float4*)ap;
        *(float4*)&a_pf[4] = *(const float4*)(ap + (size_t)64 * 512);
        const uint32_t* bp = Wt + (size_t)(bn + lr) * 512 + lc;
        b_pf[0] = *(const uint4*)bp;
        b_pf[1] = *(const uint4*)(bp + (size_t)64 * 512);
    }
    {
        *(uint4*)&As[lr * PS_ST + lc] =
            make_uint4(f2tf(a_pf[0]), f2tf(a_pf[1]), f2tf(a_pf[2]), f2tf(a_pf[3]));
        *(uint4*)&As[(lr + 64) * PS_ST + lc] =
            make_uint4(f2tf(a_pf[4]), f2tf(a_pf[5]), f2tf(a_pf[6]), f2tf(a_pf[7]));
        *(uint4*)&Bs[lr * PS_ST + lc] = b_pf[0];
        *(uint4*)&Bs[(lr + 64) * PS_ST + lc] = b_pf[1];
    }

    float c[2][8][4];
#pragma unroll
    for (int mt = 0; mt < 2; mt++)
#pragma unroll
        for (int nt = 0; nt < 8; nt++)
#pragma unroll
            for (int i = 0; i < 4; i++) c[mt][nt][i] = 0.f;

    for (int it = 0; it < 32; it++) {
        __syncthreads();
        const uint32_t* Ac = As + (it & 1) * PT_SZ;
        const uint32_t* Bc = Bs + (it & 1) * PT_SZ;

        if (it + 1 < 32) {
            int k0 = (it + 1) * 16;
            const float* ap = X + (size_t)(bm + lr) * 512 + k0 + lc;
            *(float4*)&a_pf[0] = *(const float4*)ap;
            *(float4*)&a_pf[4] = *(const float4*)(ap + (size_t)64 * 512);
            const uint32_t* bp = Wt + (size_t)(bn + lr) * 512 + k0 + lc;
            b_pf[0] = *(const uint4*)bp;
            b_pf[1] = *(const uint4*)(bp + (size_t)64 * 512);
        }

#pragma unroll
        for (int kt = 0; kt < 2; kt++) {
            uint32_t a[2][4];
            uint2 bb[8];
#pragma unroll
            for (int mt = 0; mt < 2; mt++) {
                int r = warp_m * 32 + mt * 16 + g;
                uint2 u0 = *(const uint2*)&Ac[r * PS_ST + kt * 8 + 2 * tig];
                uint2 u1 = *(const uint2*)&Ac[(r + 8) * PS_ST + kt * 8 + 2 * tig];
                a[mt][0] = u0.x; a[mt][1] = u1.x; a[mt][2] = u0.y; a[mt][3] = u1.y;
            }
#pragma unroll
            for (int nt = 0; nt < 8; nt++)
                bb[nt] = *(const uint2*)&Bc[(warp_n * 64 + nt * 8 + g) * PS_ST
                                            + kt * 8 + 2 * tig];
#pragma unroll
            for (int nt = 0; nt < 8; nt++)
#pragma unroll
                for (int mt = 0; mt < 2; mt++)
                    mma8(c[mt][nt], a[mt], (const uint32_t*)&bb[nt]);
        }

        if (it + 1 < 32) {
            uint32_t* An = As + ((it + 1) & 1) * PT_SZ;
            uint32_t* Bn = Bs + ((it + 1) & 1) * PT_SZ;
            *(uint4*)&An[lr * PS_ST + lc] =
                make_uint4(f2tf(a_pf[0]), f2tf(a_pf[1]), f2tf(a_pf[2]), f2tf(a_pf[3]));
            *(uint4*)&An[(lr + 64) * PS_ST + lc] =
                make_uint4(f2tf(a_pf[4]), f2tf(a_pf[5]), f2tf(a_pf[6]), f2tf(a_pf[7]));
            *(uint4*)&Bn[lr * PS_ST + lc] = b_pf[0];
            *(uint4*)&Bn[(lr + 64) * PS_ST + lc] = b_pf[1];
        }
    }

    // epilogue: store tf32 bits, scattered to (bt,h,l,e)
#pragma unroll
    for (int mt = 0; mt < 2; mt++) {
#pragma unroll
        for (int nt = 0; nt < 8; nt++) {
            int n = bn + warp_n * 64 + nt * 8 + 2 * tig;
            int h = n >> 6, e = n & 63;
            int r1 = bm + warp_m * 32 + mt * 16 + g;
            int bt1 = r1 >> 9, l1 = r1 & 511;
            *(uint2*)&outp[((size_t)(bt1 * 8 + h) * 512 + l1) * 64 + e] =
                make_uint2(f2tf(c[mt][nt][0]), f2tf(c[mt][nt][1]));
            int r2 = r1 + 8;
            int bt2 = r2 >> 9, l2 = r2 & 511;
            *(uint2*)&outp[((size_t)(bt2 * 8 + h) * 512 + l2) * 64 + e] =
                make_uint2(f2tf(c[mt][nt][2]), f2tf(c[mt][nt][3]));
        }
    }
}

// ---------------------------------------------------------------------------
// Flash attention per head. Q/K/V arrive as tf32 bits (no cvt here except P).
// Qs/Ks stride 72 (Qs reused as Ps), Vs stride 68. LDS.64 fragment pairs,
// batched before MMA bursts. Grid (L/64, BT, H), 128 thr / 4 warps.
// ---------------------------------------------------------------------------
#define QS_ST 72
#define VS_ST 68

__global__ __launch_bounds__(128, 3) void attn3(const float* __restrict__ mask,
                                                const float* __restrict__ w_head,
                                                const float* __restrict__ tau_p,
                                                const float* __restrict__ delta_p) {
    extern __shared__ uint32_t smu[];
    uint32_t* Qs = smu;                        // 64*72 (reused as Ps)
    uint32_t* Ks = smu + 64 * QS_ST;           // 64*72
    uint32_t* Vs = smu + 2 * 64 * QS_ST;       // 64*68

    const int tid = threadIdx.x;
    const int lane = tid & 31, wid = tid >> 5;
    const int g = lane >> 2, tig = lane & 3;
    const int bt = blockIdx.y;
    const int h  = blockIdx.z;
    const int row0 = blockIdx.x * 64;
    const int wrow = wid * 16;

    const float a_scl = tau_p[0] * 0.125f;
    const float c_add = delta_p[0] * 0.125f;

    const uint32_t* Qg = g_Q + (((size_t)(bt * 8 + h) * 512) + row0) * 64;
    const uint32_t* Kg = g_K + ((size_t)(bt * 8 + h) * 512) * 64;
    const uint32_t* Vg = g_V + ((size_t)(bt * 8 + h) * 512) * 64;

    // Q tile (raw tf32 bits)
#pragma unroll
    for (int it = 0; it < 8; it++) {
        int f = it * 128 + tid;
        int row = f >> 4, cc = (f & 15) * 4;
        *(uint4*)&Qs[row * QS_ST + cc] = *(const uint4*)(Qg + row * 64 + cc);
    }
    __syncthreads();

    // Preload Q fragments (LDS.64 pairs), then Qs becomes Ps
    uint32_t qa[8][4];
#pragma unroll
    for (int kt = 0; kt < 8; kt++) {
        uint2 u0 = *(const uint2*)&Qs[(wrow + g) * QS_ST + kt * 8 + 2 * tig];
        uint2 u1 = *(const uint2*)&Qs[(wrow + g + 8) * QS_ST + kt * 8 + 2 * tig];
        qa[kt][0] = u0.x; qa[kt][1] = u1.x; qa[kt][2] = u0.y; qa[kt][3] = u1.y;
    }

    float m1 = -INFINITY, m2 = -INFINITY, l1 = 0.f, l2 = 0.f;
    float oacc[8][4];
#pragma unroll
    for (int nt = 0; nt < 8; nt++)
#pragma unroll
        for (int i = 0; i < 4; i++) oacc[nt][i] = 0.f;

    for (int jb = 0; jb < 8; jb++) {
        __syncthreads();
#pragma unroll
        for (int it = 0; it < 8; it++) {
            int f = it * 128 + tid;
            int row = f >> 4, cc = (f & 15) * 4;
            *(uint4*)&Ks[row * QS_ST + cc] =
                *(const uint4*)(Kg + (size_t)(jb * 64 + row) * 64 + cc);
            *(uint4*)&Vs[row * VS_ST + cc] =
                *(const uint4*)(Vg + (size_t)(jb * 64 + row) * 64 + cc);
        }
        __syncthreads();

        // S = Q K^T  (batched LDS.64 then MMA burst)
        float sacc[8][4];
#pragma unroll
        for (int nt = 0; nt < 8; nt++)
#pragma unroll
            for (int i = 0; i < 4; i++) sacc[nt][i] = 0.f;
#pragma unroll
        for (int kt = 0; kt < 8; kt++) {
            uint2 kb[8];
#pragma unroll
            for (int nt = 0; nt < 8; nt++)
                kb[nt] = *(const uint2*)&Ks[(nt * 8 + g) * QS_ST + kt * 8 + 2 * tig];
#pragma unroll
            for (int nt = 0; nt < 8; nt++)
                mma8(sacc[nt], qa[kt], (const uint32_t*)&kb[nt]);
        }

        const int gr1 = row0 + wrow + g;
        const int gr2 = gr1 + 8;
#pragma unroll
        for (int nt = 0; nt < 8; nt++) {
            int gc = jb * 64 + nt * 8 + 2 * tig;
            float2 mk1 = *(const float2*)(mask + (size_t)gr1 * 512 + gc);
            float2 mk2 = *(const float2*)(mask + (size_t)gr2 * 512 + gc);
            sacc[nt][0] = fmaf(a_scl, sacc[nt][0], c_add) * mk1.x;
            sacc[nt][1] = fmaf(a_scl, sacc[nt][1], c_add) * mk1.y;
            sacc[nt][2] = fmaf(a_scl, sacc[nt][2], c_add) * mk2.x;
            sacc[nt][3] = fmaf(a_scl, sacc[nt][3], c_add) * mk2.y;
        }

        // online softmax
        float rm1 = -INFINITY, rm2 = -INFINITY;
#pragma unroll
        for (int nt = 0; nt < 8; nt++) {
            rm1 = fmaxf(rm1, fmaxf(sacc[nt][0], sacc[nt][1]));
            rm2 = fmaxf(rm2, fmaxf(sacc[nt][2], sacc[nt][3]));
        }
#pragma unroll
        for (int off = 1; off < 4; off <<= 1) {
            rm1 = fmaxf(rm1, __shfl_xor_sync(0xffffffffu, rm1, off));
            rm2 = fmaxf(rm2, __shfl_xor_sync(0xffffffffu, rm2, off));
        }
        float nm1 = fmaxf(m1, rm1), nm2 = fmaxf(m2, rm2);
        float fac1 = __expf(m1 - nm1), fac2 = __expf(m2 - nm2);
        float rs1 = 0.f, rs2 = 0.f;
#pragma unroll
        for (int nt = 0; nt < 8; nt++) {
            sacc[nt][0] = __expf(sacc[nt][0] - nm1);
            sacc[nt][1] = __expf(sacc[nt][1] - nm1);
            sacc[nt][2] = __expf(sacc[nt][2] - nm2);
            sacc[nt][3] = __expf(sacc[nt][3] - nm2);
            rs1 += sacc[nt][0] + sacc[nt][1];
            rs2 += sacc[nt][2] + sacc[nt][3];
        }
#pragma unroll
        for (int off = 1; off < 4; off <<= 1) {
            rs1 += __shfl_xor_sync(0xffffffffu, rs1, off);
            rs2 += __shfl_xor_sync(0xffffffffu, rs2, off);
        }
        l1 = l1 * fac1 + rs1;  m1 = nm1;
        l2 = l2 * fac2 + rs2;  m2 = nm2;
#pragma unroll
        for (int nt = 0; nt < 8; nt++) {
            oacc[nt][0] *= fac1;  oacc[nt][1] *= fac1;
            oacc[nt][2] *= fac2;  oacc[nt][3] *= fac2;
        }

        // stage P (tf32) into Ps=Qs (warp-private rows; adjacent cols)
#pragma unroll
        for (int nt = 0; nt < 8; nt++) {
            int cc = nt * 8 + 2 * tig;
            *(uint2*)&Qs[(wrow + g) * QS_ST + cc] =
                make_uint2(f2tf(sacc[nt][0]), f2tf(sacc[nt][1]));
            *(uint2*)&Qs[(wrow + g + 8) * QS_ST + cc] =
                make_uint2(f2tf(sacc[nt][2]), f2tf(sacc[nt][3]));
        }
        __syncwarp();

        // O += P V   (batched: pa pairs + 16 scalar vb, then MMA burst)
#pragma unroll
        for (int kt = 0; kt < 8; kt++) {
            uint32_t pa[4], vb[8][2];
            {
                uint2 u0 = *(const uint2*)&Qs[(wrow + g) * QS_ST + kt * 8 + 2 * tig];
                uint2 u1 = *(const uint2*)&Qs[(wrow + g + 8) * QS_ST + kt * 8 + 2 * tig];
                pa[0] = u0.x; pa[1] = u1.x; pa[2] = u0.y; pa[3] = u1.y;
            }
#pragma unroll
            for (int nt = 0; nt < 8; nt++) {
                vb[nt][0] = Vs[(kt * 8 + 2 * tig) * VS_ST + nt * 8 + g];
                vb[nt][1] = Vs[(kt * 8 + 2 * tig + 1) * VS_ST + nt * 8 + g];
            }
#pragma unroll
            for (int nt = 0; nt < 8; nt++)
                mma8(oacc[nt], pa, vb[nt]);
        }
    }

    const float wh = w_head[h];
    const float i1 = wh / l1, i2 = wh / l2;
    float* po = g_part + (size_t)h * OUTN;
    const int l1r = row0 + wrow + g, l2r = l1r + 8;
#pragma unroll
    for (int nt = 0; nt < 8; nt++) {
        int e = nt * 8 + 2 * tig;
        *(float2*)&po[((size_t)bt * 512 + l1r) * 64 + e] =
            make_float2(oacc[nt][0] * i1, oacc[nt][1] * i1);
        *(float2*)&po[((size_t)bt * 512 + l2r) * 64 + e] =
            make_float2(oacc[nt][2] * i2, oacc[nt][3] * i2);
    }
}

__global__ __launch_bounds__(256) void reduce_out(float* __restrict__ out) {
    int i = blockIdx.x * 256 + threadIdx.x;
    const float4* p = (const float4*)g_part;
    float4 s = p[i];
#pragma unroll
    for (int h = 1; h < 8; h++) {
        float4 t = p[(size_t)h * (OUTN / 4) + i];
        s.x += t.x; s.y += t.y; s.z += t.z; s.w += t.w;
    }
    ((float4*)out)[i] = s;
}

extern "C" void kernel_launch(void* const* d_in, const int* in_sizes, int n_in,
                              void* d_out, int out_size) {
    const float* queries = (const float*)d_in[0];
    const float* keys    = (const float*)d_in[1];
    const float* values  = (const float*)d_in[2];
    const float* mask    = (const float*)d_in[3];
    const float* Wq      = (const float*)d_in[4];
    const float* Wk      = (const float*)d_in[5];
    const float* Wv      = (const float*)d_in[6];
    const float* w_head  = (const float*)d_in[7];
    const float* tau     = (const float*)d_in[8];
    const float* delta   = (const float*)d_in[9];
    float* out = (float*)d_out;

    dim3 wgrid(8, 8, 3);
    wtrans<<<wgrid, 256>>>(Wq, Wk, Wv);

    const int psmem = 4 * PT_SZ * (int)sizeof(uint32_t);   // 81920 B
    cudaFuncSetAttribute(proj3, cudaFuncAttributeMaxDynamicSharedMemorySize, psmem);
    dim3 pgrid(128, 4, 3);
    proj3<<<pgrid, 256, psmem>>>(queries, keys, values);

    const int asmem = (2 * 64 * QS_ST + 64 * VS_ST) * (int)sizeof(uint32_t);  // 54272 B
    cudaFuncSetAttribute(attn3, cudaFuncAttributeMaxDynamicSharedMemorySize, asmem);
    dim3 agrid(8, 32, 8);
    attn3<<<agrid, 128, asmem>>>(mask, w_head, tau, delta);

    reduce_out<<<OUTN / 4 / 256, 256>>>(out);
}